// round 1
// baseline (speedup 1.0000x reference)
#include <cuda_runtime.h>
#include <float.h>

// Problem constants
#define BATCH   16
#define CDIM    256
#define HW      1024            // 32*32
#define NROWS   16384           // BATCH*HW
#define KCODES  8192
#define NELEM   4194304         // BATCH*CDIM*HW

// GEMM tiling
#define BM      128
#define BN      128
#define BKC     16
#define BNP     136             // padded Bs row (multiple of 4 for float4 reads)

// Scratch (no cudaMalloc allowed)
__device__ int   g_codes[NROWS];
__device__ float g_esq[KCODES];
__device__ float g_zsq[NROWS];
__device__ float g_partial[NELEM / 256];

// ---------------------------------------------------------------------------
// e_sq[k] = sum_c codebook[k][c]^2        (one warp per code)
// ---------------------------------------------------------------------------
__global__ void vq_esq_kernel(const float* __restrict__ cbk) {
    int k    = blockIdx.x * 8 + (threadIdx.x >> 5);
    int lane = threadIdx.x & 31;
    const float4* row = (const float4*)(cbk + (size_t)k * CDIM);
    float s = 0.f;
    #pragma unroll
    for (int i = lane; i < CDIM / 4; i += 32) {
        float4 v = row[i];
        s += v.x * v.x + v.y * v.y + v.z * v.z + v.w * v.w;
    }
    #pragma unroll
    for (int off = 16; off > 0; off >>= 1)
        s += __shfl_down_sync(0xffffffffu, s, off);
    if (lane == 0) g_esq[k] = s;
}

// ---------------------------------------------------------------------------
// z_sq[n] = sum_c z[b][c][hw]^2           (one thread per row, coalesced in hw)
// ---------------------------------------------------------------------------
__global__ void vq_zsq_kernel(const float* __restrict__ z) {
    int n  = blockIdx.x * 256 + threadIdx.x;
    int b  = n >> 10;
    int hw = n & 1023;
    const float* p = z + (size_t)b * CDIM * HW + hw;
    float s = 0.f;
    #pragma unroll 8
    for (int c = 0; c < CDIM; c++) {
        float v = p[(size_t)c * HW];
        s += v * v;
    }
    g_zsq[n] = s;
}

// ---------------------------------------------------------------------------
// Fused GEMM + argmin: per-row argmin_k of (z_sq - 2*cross + e_sq).
// A panel (128 rows x 256 C) resident in SMEM; codes streamed in 128-chunks.
// ---------------------------------------------------------------------------
__global__ __launch_bounds__(256, 1)
void vq_main_kernel(const float* __restrict__ z, const float* __restrict__ cbk,
                    float* __restrict__ out_codes_f) {
    extern __shared__ float sm[];
    float* As   = sm;                                  // 32768 floats (128KB)
    float* Bs   = sm + CDIM * BM;                      // BKC*BNP floats
    float* redv = Bs + BKC * BNP;                      // 128*16 floats
    int*   redi = (int*)(redv + BM * 16);              // 128*16 ints

    const int tid = threadIdx.x;
    const int tx  = tid & 15;
    const int ty  = tid >> 4;
    const int rowbase = blockIdx.x * BM;
    const int b   = rowbase >> 10;
    const int hw0 = rowbase & 1023;

    // Load A panel: As[c*128 + r] = z[b][c][hw0 + r]  (fully coalesced float4)
    {
        const float* zb = z + (size_t)b * CDIM * HW + hw0;
        float4* As4 = (float4*)As;
        for (int idx = tid; idx < CDIM * (BM / 4); idx += 256) {
            int c = idx >> 5;          // BM/4 = 32 float4 per c-row
            int q = idx & 31;
            As4[idx] = *(const float4*)(zb + (size_t)c * HW + q * 4);
        }
    }

    const int r0 = ty * 8;
    float zs[8];
    #pragma unroll
    for (int i = 0; i < 8; i++) zs[i] = g_zsq[rowbase + r0 + i];

    float rmin[8];
    int   ridx[8];
    #pragma unroll
    for (int i = 0; i < 8; i++) { rmin[i] = FLT_MAX; ridx[i] = 0; }

    __syncthreads();

    const float4* cb4 = (const float4*)cbk;

    for (int cb0 = 0; cb0 < KCODES; cb0 += BN) {
        float acc[8][8];
        #pragma unroll
        for (int i = 0; i < 8; i++)
            #pragma unroll
            for (int j = 0; j < 8; j++) acc[i][j] = 0.f;

        for (int kc = 0; kc < CDIM; kc += BKC) {
            __syncthreads();
            // Load + transpose B chunk: Bs[c'][code], c' in [0,16), code in [0,128)
            for (int idx = tid; idx < 512; idx += 256) {
                int code = idx >> 2;
                int cq   = idx & 3;
                float4 v = cb4[(size_t)(cb0 + code) * (CDIM / 4) + (kc >> 2) + cq];
                int c0 = cq * 4;
                Bs[(c0 + 0) * BNP + code] = v.x;
                Bs[(c0 + 1) * BNP + code] = v.y;
                Bs[(c0 + 2) * BNP + code] = v.z;
                Bs[(c0 + 3) * BNP + code] = v.w;
            }
            __syncthreads();

            #pragma unroll 4
            for (int k = 0; k < BKC; k++) {
                const float4* arow = (const float4*)(As + (size_t)(kc + k) * BM);
                float4 a0 = arow[ty * 2];
                float4 a1 = arow[ty * 2 + 1];
                float4 b0 = *(const float4*)(Bs + k * BNP + tx * 8);
                float4 b1 = *(const float4*)(Bs + k * BNP + tx * 8 + 4);
                float av[8] = {a0.x, a0.y, a0.z, a0.w, a1.x, a1.y, a1.z, a1.w};
                float bv[8] = {b0.x, b0.y, b0.z, b0.w, b1.x, b1.y, b1.z, b1.w};
                #pragma unroll
                for (int i = 0; i < 8; i++)
                    #pragma unroll
                    for (int j = 0; j < 8; j++)
                        acc[i][j] += av[i] * bv[j];
            }
        }

        // Epilogue: distances + running argmin (cols ascend within thread ->
        // strict < reproduces first-index tie-break for this thread's cols)
        #pragma unroll
        for (int j = 0; j < 8; j++) {
            int col  = cb0 + tx * 8 + j;
            float es = g_esq[col];
            #pragma unroll
            for (int i = 0; i < 8; i++) {
                // match reference rounding: (z_sq - 2*cross) + e_sq
                float t = zs[i] - 2.0f * acc[i][j];
                float d = t + es;
                if (d < rmin[i]) { rmin[i] = d; ridx[i] = col; }
            }
        }
    }

    // Cross-thread (tx) reduction per row with first-index tie-break
    __syncthreads();
    #pragma unroll
    for (int i = 0; i < 8; i++) {
        redv[(r0 + i) * 16 + tx] = rmin[i];
        redi[(r0 + i) * 16 + tx] = ridx[i];
    }
    __syncthreads();
    if (tid < BM) {
        int r = tid;
        float best = redv[r * 16];
        int   bi   = redi[r * 16];
        #pragma unroll
        for (int t = 1; t < 16; t++) {
            float v  = redv[r * 16 + t];
            int   ix = redi[r * 16 + t];
            if (v < best || (v == best && ix < bi)) { best = v; bi = ix; }
        }
        g_codes[rowbase + r]      = bi;
        out_codes_f[rowbase + r]  = (float)bi;
    }
}

// ---------------------------------------------------------------------------
// Gather quantized output (straight-through: z + (q - z), exact ref rounding)
// and accumulate per-block partial sums of (q - z)^2.
// ---------------------------------------------------------------------------
__global__ void vq_gather_kernel(const float* __restrict__ z,
                                 const float* __restrict__ cbk,
                                 float* __restrict__ out_q) {
    __shared__ float sred[256];
    int o  = blockIdx.x * 256 + threadIdx.x;
    int hw = o & 1023;
    int c  = (o >> 10) & 255;
    int b  = o >> 18;
    int code = g_codes[(b << 10) + hw];
    float q  = __ldg(&cbk[(size_t)code * CDIM + c]);
    float zv = z[o];
    float qz = q - zv;
    out_q[o] = zv + qz;                 // straight-through numeric path
    sred[threadIdx.x] = qz * qz;
    __syncthreads();
    #pragma unroll
    for (int off = 128; off > 0; off >>= 1) {
        if (threadIdx.x < off) sred[threadIdx.x] += sred[threadIdx.x + off];
        __syncthreads();
    }
    if (threadIdx.x == 0) g_partial[blockIdx.x] = sred[0];
}

// ---------------------------------------------------------------------------
// Deterministic final reduction: vq_loss = 1.25 * mean((q - z)^2)
// ---------------------------------------------------------------------------
__global__ void vq_finalize_kernel(float* __restrict__ out_loss) {
    __shared__ float s[256];
    float a = 0.f;
    for (int i = threadIdx.x; i < NELEM / 256; i += 256) a += g_partial[i];
    s[threadIdx.x] = a;
    __syncthreads();
    #pragma unroll
    for (int off = 128; off > 0; off >>= 1) {
        if (threadIdx.x < off) s[threadIdx.x] += s[threadIdx.x + off];
        __syncthreads();
    }
    if (threadIdx.x == 0)
        out_loss[0] = s[0] * (1.25f / (float)NELEM);
}

// ---------------------------------------------------------------------------
extern "C" void kernel_launch(void* const* d_in, const int* in_sizes, int n_in,
                              void* d_out, int out_size) {
    const float* z   = (const float*)d_in[0];   // (16,256,32,32) f32
    const float* cbk = (const float*)d_in[1];   // (8192,256) f32

    float* out        = (float*)d_out;
    float* out_codes  = out;                     // 16384 floats
    float* out_q      = out + NROWS;             // 4194304 floats
    float* out_loss   = out + NROWS + NELEM;     // 1 float

    const size_t SMEM = (size_t)(CDIM * BM + BKC * BNP + BM * 16) * sizeof(float)
                      + (size_t)(BM * 16) * sizeof(int);
    cudaFuncSetAttribute(vq_main_kernel,
                         cudaFuncAttributeMaxDynamicSharedMemorySize, (int)SMEM);

    vq_esq_kernel<<<KCODES / 8, 256>>>(cbk);
    vq_zsq_kernel<<<NROWS / 256, 256>>>(z);
    vq_main_kernel<<<NROWS / BM, 256, SMEM>>>(z, cbk, out_codes);
    vq_gather_kernel<<<NELEM / 256, 256>>>(z, cbk, out_q);
    vq_finalize_kernel<<<1, 256>>>(out_loss);
}